// round 1
// baseline (speedup 1.0000x reference)
#include <cuda_runtime.h>
#include <math.h>

#define D_EMBED 128
#define NHEAD   4
#define HD      32
#define NTOK    4096
#define BATCH   4

// Scratch: [part(q,k,v)][b][head][tok][hd]
__device__ float g_qkv[3u * BATCH * NHEAD * NTOK * HD];

__device__ __forceinline__ float fast_exp2(float x) {
    float y;
    asm("ex2.approx.ftz.f32 %0, %1;" : "=f"(y) : "f"(x));
    return y;
}

// ---------------------------------------------------------------------------
// QKV projection: qkv[b,n,3c] = t @ W + bias, scattered into head-major Q/K/V.
// Block computes 64 tokens x 64 output cols. grid = (256 token tiles, 6 col tiles)
// ---------------------------------------------------------------------------
__global__ __launch_bounds__(256) void qkv_kernel(const float* __restrict__ x,
                                                  const float* __restrict__ W,
                                                  const float* __restrict__ bias) {
    __shared__ float tS[32][68];  // [k][token], padded for float4-aligned, conflict-free reads
    __shared__ float wS[32][68];  // [k][col]

    const int tid = threadIdx.x;
    const int m0 = blockIdx.x * 64;       // global token row (within b*n)
    const int b = m0 / NTOK;
    const int pix0 = m0 % NTOK;
    const int col0 = blockIdx.y * 64;

    const float* xb = x + (size_t)b * D_EMBED * NTOK;

    float acc[4][4] = {};
    const int r0 = (tid >> 4) << 2;
    const int c0 = (tid & 15) << 2;

    for (int k0 = 0; k0 < D_EMBED; k0 += 32) {
        __syncthreads();
        for (int idx = tid; idx < 32 * 64; idx += 256) {
            int k = idx >> 6, r = idx & 63;
            tS[k][r] = xb[(size_t)(k0 + k) * NTOK + pix0 + r];
        }
        for (int idx = tid; idx < 32 * 64; idx += 256) {
            int k = idx >> 6, c = idx & 63;
            wS[k][c] = W[(k0 + k) * 384 + col0 + c];
        }
        __syncthreads();

        #pragma unroll
        for (int kk = 0; kk < 32; kk++) {
            float4 a = *(const float4*)&tS[kk][r0];
            float4 w4 = *(const float4*)&wS[kk][c0];
            float av[4] = {a.x, a.y, a.z, a.w};
            float wv[4] = {w4.x, w4.y, w4.z, w4.w};
            #pragma unroll
            for (int i = 0; i < 4; i++)
                #pragma unroll
                for (int j = 0; j < 4; j++)
                    acc[i][j] = fmaf(av[i], wv[j], acc[i][j]);
        }
    }

    // bias + scatter into g_qkv [part][b][head][tok][hd]
    const int colg = col0 + c0;            // 4 consecutive cols, same part & head
    const int part = colg / 128;
    const int rem  = colg % 128;
    const int head = rem >> 5;
    const int d    = rem & 31;
    float4 bv = *(const float4*)&bias[colg];
    float* dstBase = g_qkv + ((((size_t)part * BATCH + b) * NHEAD + head) * NTOK) * HD + d;

    #pragma unroll
    for (int i = 0; i < 4; i++) {
        int pix = pix0 + r0 + i;
        float4 v;
        v.x = acc[i][0] + bv.x;
        v.y = acc[i][1] + bv.y;
        v.z = acc[i][2] + bv.z;
        v.w = acc[i][3] + bv.w;
        *(float4*)(dstBase + (size_t)pix * HD) = v;
    }
}

// ---------------------------------------------------------------------------
// Flash attention, 64-query x 64-key tiles, fp32, online softmax in base-2.
// grid = (64 q-tiles, 4 heads, 4 batch), 256 threads.
// Epilogue fuses the raw-reshape + residual: L = tok*128 + head*32 + d.
// ---------------------------------------------------------------------------
__global__ __launch_bounds__(256) void attn_kernel(const float* __restrict__ x,
                                                   float* __restrict__ out) {
    __shared__ float Qs[32][68];   // [d][qrow], pre-scaled
    __shared__ float Ks[32][68];   // [d][key]
    __shared__ float Vs[64][32];   // [key][d]
    __shared__ float Ps[64][65];   // scores -> probabilities

    const int tid = threadIdx.x;
    const int q0 = blockIdx.x * 64;
    const int h  = blockIdx.y;
    const int b  = blockIdx.z;

    const size_t headStride = (size_t)NTOK * HD;
    const float* Qg = g_qkv + (((size_t)0 * BATCH + b) * NHEAD + h) * headStride;
    const float* Kg = g_qkv + (((size_t)1 * BATCH + b) * NHEAD + h) * headStride;
    const float* Vg = g_qkv + (((size_t)2 * BATCH + b) * NHEAD + h) * headStride;

    // fold 1/sqrt(hd) and log2(e) into Q so softmax runs in base-2
    const float qscale = 0.17677669529663687f * 1.4426950408889634f;

    for (int idx = tid; idx < 64 * 32; idx += 256) {
        int pix = idx >> 5, d = idx & 31;
        Qs[d][pix] = Qg[(size_t)(q0 + pix) * HD + d] * qscale;
    }

    const int row = tid >> 2;            // query row owned in softmax / O phases
    const int seg = tid & 3;
    const int d0  = seg * 8;             // 8 output dims owned
    float m = -1e30f, l = 0.0f;
    float o[8] = {0, 0, 0, 0, 0, 0, 0, 0};

    const int r0  = (tid >> 4) << 2;     // S-compute micro-tile
    const int c0s = (tid & 15) << 2;

    for (int j = 0; j < NTOK / 64; j++) {
        __syncthreads();                 // prev-iter consumers of Ks/Vs/Ps done
        const int k0 = j * 64;

        for (int idx = tid; idx < 64 * 32; idx += 256) {
            int key = idx >> 5, d = idx & 31;
            Ks[d][key] = Kg[(size_t)(k0 + key) * HD + d];
        }
        {
            const float4* vsrc = (const float4*)(Vg + (size_t)k0 * HD);
            float4* vdst = (float4*)&Vs[0][0];
            for (int idx = tid; idx < 64 * 32 / 4; idx += 256)
                vdst[idx] = vsrc[idx];
        }
        __syncthreads();

        // S = Q K^T (base-2 scaled), 4x4 per thread
        float acc[4][4] = {};
        #pragma unroll
        for (int kk = 0; kk < 32; kk++) {
            float4 qa = *(const float4*)&Qs[kk][r0];
            float4 kb = *(const float4*)&Ks[kk][c0s];
            float qv[4] = {qa.x, qa.y, qa.z, qa.w};
            float kv[4] = {kb.x, kb.y, kb.z, kb.w};
            #pragma unroll
            for (int i = 0; i < 4; i++)
                #pragma unroll
                for (int jj = 0; jj < 4; jj++)
                    acc[i][jj] = fmaf(qv[i], kv[jj], acc[i][jj]);
        }
        #pragma unroll
        for (int i = 0; i < 4; i++)
            #pragma unroll
            for (int jj = 0; jj < 4; jj++)
                Ps[r0 + i][c0s + jj] = acc[i][jj];
        __syncthreads();

        // online softmax: quad (4 threads) per row, stats in registers
        float mt = -1e30f;
        #pragma unroll
        for (int c = 0; c < 16; c++)
            mt = fmaxf(mt, Ps[row][seg * 16 + c]);
        mt = fmaxf(mt, __shfl_xor_sync(0xffffffffu, mt, 1));
        mt = fmaxf(mt, __shfl_xor_sync(0xffffffffu, mt, 2));
        float mnew = fmaxf(m, mt);
        float alpha = fast_exp2(m - mnew);
        float ssum = 0.0f;
        #pragma unroll
        for (int c = 0; c < 16; c++) {
            float p = fast_exp2(Ps[row][seg * 16 + c] - mnew);
            Ps[row][seg * 16 + c] = p;
            ssum += p;
        }
        ssum += __shfl_xor_sync(0xffffffffu, ssum, 1);
        ssum += __shfl_xor_sync(0xffffffffu, ssum, 2);
        l = l * alpha + ssum;
        m = mnew;
        __syncwarp();                    // quad siblings' P segments visible

        // O = O*alpha + P V
        #pragma unroll
        for (int i = 0; i < 8; i++) o[i] *= alpha;
        #pragma unroll 4
        for (int c = 0; c < 64; c++) {
            float p = Ps[row][c];
            const float4* vrow = (const float4*)&Vs[c][d0];
            float4 v0 = vrow[0], v1 = vrow[1];
            o[0] = fmaf(p, v0.x, o[0]);
            o[1] = fmaf(p, v0.y, o[1]);
            o[2] = fmaf(p, v0.z, o[2]);
            o[3] = fmaf(p, v0.w, o[3]);
            o[4] = fmaf(p, v1.x, o[4]);
            o[5] = fmaf(p, v1.y, o[5]);
            o[6] = fmaf(p, v1.z, o[6]);
            o[7] = fmaf(p, v1.w, o[7]);
        }
    }

    // epilogue: raw reshape (L = tok*128 + h*32 + d) + residual
    const float inv = 1.0f / l;
    const int tok = q0 + row;
    const size_t base = (size_t)b * (128 * NTOK) + (size_t)tok * 128 + h * 32 + d0;
    #pragma unroll
    for (int i = 0; i < 8; i++)
        out[base + i] = o[i] * inv + x[base + i];
}

extern "C" void kernel_launch(void* const* d_in, const int* in_sizes, int n_in,
                              void* d_out, int out_size) {
    const float* x    = (const float*)d_in[0];
    const float* W    = (const float*)d_in[1];
    const float* bias = (const float*)d_in[2];
    float* out = (float*)d_out;

    dim3 gQKV(BATCH * NTOK / 64, 384 / 64);
    qkv_kernel<<<gQKV, 256>>>(x, W, bias);

    dim3 gAttn(NTOK / 64, NHEAD, BATCH);
    attn_kernel<<<gAttn, 256>>>(x, out);
}